// round 11
// baseline (speedup 1.0000x reference)
#include <cuda_runtime.h>
#include <cstdint>
#include <math.h>

#define BB 8
#define HH 96
#define WW 96
#define DD 768
#define NN (HH*WW)
#define STR 36             // smem row stride (floats), ==4 mod 32 -> conflict-free frags
#define AROWS 128
#define ROWS 368           // 128 A rows + 240 B halo rows (20x12)
#define BUFF (ROWS*STR)    // 13248 floats per buffer
#define NCHK 24            // K chunks of 32 floats
#define S_NRM (2*BUFF)
#define S_RED (S_NRM+ROWS)
#define SMEMF (S_RED+48)   // 26912 floats = 107648 B
#define SIMSTR 76
#define NBLK 576
#define TFM(x) __uint_as_float(__float_as_uint(x) & 0xFFFFE000u)

__device__ float g_part[5][NBLK];
__device__ int g_cnt = 0;
extern __shared__ float smem[];

__device__ __forceinline__ void mma8(float* d, uint32_t a0, uint32_t a1,
                                     uint32_t a2, uint32_t a3,
                                     uint32_t b0, uint32_t b1) {
  asm volatile(
    "mma.sync.aligned.m16n8k8.row.col.f32.tf32.tf32.f32 "
    "{%0,%1,%2,%3}, {%4,%5,%6,%7}, {%8,%9}, {%0,%1,%2,%3};"
    : "+f"(d[0]), "+f"(d[1]), "+f"(d[2]), "+f"(d[3])
    : "r"(a0), "r"(a1), "r"(a2), "r"(a3), "r"(b0), "r"(b1));
}

__global__ void __launch_bounds__(256, 2)
align_kernel(const float* __restrict__ z1, const float* __restrict__ z2,
             const float* __restrict__ w1, const float* __restrict__ w2,
             float* __restrict__ out)
{
  const int tid = threadIdx.x, w = tid >> 5, lane = tid & 31, lane8 = tid & 7;
  const int b = blockIdx.z, th0 = blockIdx.y * 16, tw0 = blockIdx.x * 8;

  // ---- A staging: affine in slot k (rows arow+32k, k=0..3) -----------------
  const int arow = tid >> 3;
  const int aty  = tid >> 6;
  const int atx  = (tid >> 3) & 7;
  const int agBase  = (b*NN + (th0+aty)*WW + tw0+atx)*DD + lane8*4;
  const int agStep  = 4*WW*DD;
  const int sofBase = arow*STR + lane8*4;
  const int sofStep = 32*STR;

  // ---- B staging: slot k=0..7 -> halo row n = arow + 32k -------------------
  int bg[8];
#pragma unroll
  for (int k = 0; k < 8; k++) {
    int n = arow + 32*k;
    if (n < 240) {
      int r = n/12, cl = n - 12*r;
      int gh = th0 + r - 2, gw = tw0 + cl - 2;
      bool inb = ((unsigned)gh < HH) && ((unsigned)gw < WW);
      bg[k] = inb ? (b*NN + gh*WW + gw)*DD + lane8*4 : -1;
    } else bg[k] = -2;
  }
  float nrmA[4] = {0,0,0,0};
  float nrmB[8] = {0,0,0,0,0,0,0,0};
  float acc[9][4];
#pragma unroll
  for (int j = 0; j < 9; j++)
#pragma unroll
    for (int i = 0; i < 4; i++) acc[j][i] = 0.f;

  const int aOff = (16*w + (lane >> 2))*STR + (lane & 3);
  const int bOff = (AROWS + 24*w + (lane >> 2))*STR + (lane & 3);

  // ---- prologue: zero OOB halo rows in BOTH buffers ------------------------
#pragma unroll
  for (int k = 0; k < 8; k++)
    if (bg[k] == -1) {
      int sof = sofBase + (4+k)*sofStep;
      *(float4*)(smem + sof)        = make_float4(0.f,0.f,0.f,0.f);
      *(float4*)(smem + BUFF + sof) = make_float4(0.f,0.f,0.f,0.f);
    }
  // stage chunk 0 into buf0
#pragma unroll
  for (int k = 0; k < 4; k++) {
    float4 v = *(const float4*)(z1 + agBase + k*agStep);
    v.x=TFM(v.x); v.y=TFM(v.y); v.z=TFM(v.z); v.w=TFM(v.w);
    nrmA[k] += v.x*v.x + v.y*v.y + v.z*v.z + v.w*v.w;
    *(float4*)(smem + sofBase + k*sofStep) = v;
  }
#pragma unroll
  for (int k = 0; k < 8; k++)
    if (bg[k] >= 0) {
      float4 v = *(const float4*)(z2 + bg[k]);
      v.x=TFM(v.x); v.y=TFM(v.y); v.z=TFM(v.z); v.w=TFM(v.w);
      nrmB[k] += v.x*v.x + v.y*v.y + v.z*v.z + v.w*v.w;
      *(float4*)(smem + sofBase + (4+k)*sofStep) = v;
    }
  __syncthreads();

  // ---- main loop: full-chunk LDG lead ---------------------------------------
#pragma unroll 1
  for (int c = 0; c < NCHK; c++) {
    const uint32_t* A = (const uint32_t*)(smem + (c & 1)*BUFF) + aOff;
    const uint32_t* B = (const uint32_t*)(smem + (c & 1)*BUFF) + bOff;
    float* nb = smem + ((c + 1) & 1)*BUFF;
    const bool more = (c + 1 < NCHK);
    const int co = (c + 1)*32;
    float4 za[4], zb[6];

    // issue A(0..3) + B(0..5) loads for chunk c+1 at the very top
    if (more) {
#pragma unroll
      for (int k = 0; k < 4; k++)
        za[k] = *(const float4*)(z1 + agBase + k*agStep + co);
#pragma unroll
      for (int k = 0; k < 6; k++)
        if (bg[k] >= 0) zb[k] = *(const float4*)(z2 + bg[k] + co);
    }
    // MMA kt = 0,1
#pragma unroll
    for (int kt = 0; kt < 2; kt++) {
      uint32_t a0 = A[kt*8],     a1 = A[8*STR + kt*8];
      uint32_t a2 = A[kt*8 + 4], a3 = A[8*STR + kt*8 + 4];
#pragma unroll
      for (int j = 0; j < 9; j++)
        mma8(acc[j], a0, a1, a2, a3, B[j*8*STR + kt*8], B[j*8*STR + kt*8 + 4]);
    }
    // STS A(0..3) + B(0..1); then reuse zb[0..1] for B(6..7) loads
    if (more) {
#pragma unroll
      for (int k = 0; k < 4; k++) {
        float4 v = za[k];
        v.x=TFM(v.x); v.y=TFM(v.y); v.z=TFM(v.z); v.w=TFM(v.w);
        nrmA[k] += v.x*v.x + v.y*v.y + v.z*v.z + v.w*v.w;
        *(float4*)(nb + sofBase + k*sofStep) = v;
      }
#pragma unroll
      for (int k = 0; k < 2; k++)
        if (bg[k] >= 0) {
          float4 v = zb[k];
          v.x=TFM(v.x); v.y=TFM(v.y); v.z=TFM(v.z); v.w=TFM(v.w);
          nrmB[k] += v.x*v.x + v.y*v.y + v.z*v.z + v.w*v.w;
          *(float4*)(nb + sofBase + (4+k)*sofStep) = v;
        }
#pragma unroll
      for (int k = 6; k < 8; k++)
        if (bg[k] >= 0) zb[k-6] = *(const float4*)(z2 + bg[k] + co);
    }
    // MMA kt = 2,3
#pragma unroll
    for (int kt = 2; kt < 4; kt++) {
      uint32_t a0 = A[kt*8],     a1 = A[8*STR + kt*8];
      uint32_t a2 = A[kt*8 + 4], a3 = A[8*STR + kt*8 + 4];
#pragma unroll
      for (int j = 0; j < 9; j++)
        mma8(acc[j], a0, a1, a2, a3, B[j*8*STR + kt*8], B[j*8*STR + kt*8 + 4]);
    }
    // STS B(2..5) + B(6..7)
    if (more) {
#pragma unroll
      for (int k = 2; k < 6; k++)
        if (bg[k] >= 0) {
          float4 v = zb[k];
          v.x=TFM(v.x); v.y=TFM(v.y); v.z=TFM(v.z); v.w=TFM(v.w);
          nrmB[k] += v.x*v.x + v.y*v.y + v.z*v.z + v.w*v.w;
          *(float4*)(nb + sofBase + (4+k)*sofStep) = v;
        }
#pragma unroll
      for (int k = 6; k < 8; k++)
        if (bg[k] >= 0) {
          float4 v = zb[k-6];
          v.x=TFM(v.x); v.y=TFM(v.y); v.z=TFM(v.z); v.w=TFM(v.w);
          nrmB[k] += v.x*v.x + v.y*v.y + v.z*v.z + v.w*v.w;
          *(float4*)(nb + sofBase + (4+k)*sofStep) = v;
        }
    }
    __syncthreads();
  }

  // ---- norms: reduce 8 lanes per row -> S_NRM ------------------------------
#pragma unroll
  for (int k = 0; k < 4; k++) {
    float r = nrmA[k];
    r += __shfl_down_sync(0xffffffffu, r, 4);
    r += __shfl_down_sync(0xffffffffu, r, 2);
    r += __shfl_down_sync(0xffffffffu, r, 1);
    if (lane8 == 0) smem[S_NRM + arow + 32*k] = r;
  }
#pragma unroll
  for (int k = 0; k < 8; k++) {
    float r = nrmB[k];
    r += __shfl_down_sync(0xffffffffu, r, 4);
    r += __shfl_down_sync(0xffffffffu, r, 2);
    r += __shfl_down_sync(0xffffffffu, r, 1);
    int row = AROWS + arow + 32*k;
    if (lane8 == 0 && row < ROWS) smem[S_NRM + row] = r;
  }

  // ---- sims -> smem (reuse buf0 region), stride 76 -------------------------
  {
    float* sims = smem;
    int row0 = 16*w + (lane >> 2);
    int cc = 2*(lane & 3);
#pragma unroll
    for (int j = 0; j < 9; j++) {
      *(float2*)(sims + row0*SIMSTR + 8*j + cc)     = make_float2(acc[j][0], acc[j][1]);
      *(float2*)(sims + (row0+8)*SIMSTR + 8*j + cc) = make_float2(acc[j][2], acc[j][3]);
    }
  }
  __syncthreads();

  for (int t = tid; t < ROWS; t += 256) {
    float v = smem[S_NRM + t];
    smem[S_NRM + t] = 1.f / fmaxf(sqrtf(v), 1e-12f);
  }
  __syncthreads();

  // ---- epilogue: per-token 25-shift softmax + weighted partials ------------
  float pA1 = 0.f, pA2 = 0.f, pP = 0.f, pS1 = 0.f, pS2 = 0.f;
  if (tid < AROWS) {
    int m = tid, ty = m >> 3, tx = m & 7;
    int mw = m >> 4;
    int tprime = (m >> 3) & 1;
    const float inv1 = smem[S_NRM + m];
    const float* srow = smem + m*SIMSTR;
    const float* invB = smem + S_NRM + AROWS + 24*mw;
    float sn[25], mx = -1e30f;
#pragma unroll
    for (int dy = 0; dy < 5; dy++)
#pragma unroll
      for (int dx = 0; dx < 5; dx++) {
        int nl = (tprime + dy)*12 + tx + dx;
        float v = srow[nl] * inv1 * invB[nl];
        sn[dy*5 + dx] = v; mx = fmaxf(mx, v);
      }
    float se = 0.f, sv = 0.f;
    const float invT = 1.f / 0.07f;
#pragma unroll
    for (int s = 0; s < 25; s++) {
      float e = __expf((sn[s] - mx) * invT);
      se += e; sv += e * sn[s];
    }
    float sb = sv / se;
    int tok = (th0 + ty)*WW + tw0 + tx;
    float wv1 = w1[b*NN + tok], wv2 = w2[b*NN + tok];
    pA1 = (1.f - sb)*wv1; pA2 = (1.f - sb)*wv2; pP = sb; pS1 = wv1; pS2 = wv2;
  }
#pragma unroll
  for (int o = 16; o > 0; o >>= 1) {
    pA1 += __shfl_down_sync(0xffffffffu, pA1, o);
    pA2 += __shfl_down_sync(0xffffffffu, pA2, o);
    pP  += __shfl_down_sync(0xffffffffu, pP,  o);
    pS1 += __shfl_down_sync(0xffffffffu, pS1, o);
    pS2 += __shfl_down_sync(0xffffffffu, pS2, o);
  }
  float* red = smem + S_RED;
  if (lane == 0) {
    red[w] = pA1; red[8+w] = pA2; red[16+w] = pP; red[24+w] = pS1; red[32+w] = pS2;
  }
  __syncthreads();
  if (tid == 0) {
    float a1=0,a2=0,p=0,s1=0,s2=0;
#pragma unroll
    for (int i = 0; i < 8; i++) {
      a1+=red[i]; a2+=red[8+i]; p+=red[16+i]; s1+=red[24+i]; s2+=red[32+i];
    }
    int bid = blockIdx.x + 12*blockIdx.y + 72*blockIdx.z;
    g_part[0][bid]=a1; g_part[1][bid]=a2; g_part[2][bid]=p;
    g_part[3][bid]=s1; g_part[4][bid]=s2;
    __threadfence();
    int t = atomicAdd(&g_cnt, 1);
    red[45] = (t == NBLK-1) ? 1.f : 0.f;
  }
  __syncthreads();

  // ---- last block performs the deterministic final reduction ---------------
  if (red[45] != 0.f) {
    int fw = tid >> 5, flane = tid & 31;
    float a1=0,a2=0,p=0,s1=0,s2=0;
    if (fw < BB) {
      for (int i = flane; i < 72; i += 32) {
        int bid = fw*72 + i;
        a1 += g_part[0][bid]; a2 += g_part[1][bid]; p += g_part[2][bid];
        s1 += g_part[3][bid]; s2 += g_part[4][bid];
      }
    }
#pragma unroll
    for (int o = 16; o > 0; o >>= 1) {
      a1 += __shfl_down_sync(0xffffffffu, a1, o);
      a2 += __shfl_down_sync(0xffffffffu, a2, o);
      p  += __shfl_down_sync(0xffffffffu, p,  o);
      s1 += __shfl_down_sync(0xffffffffu, s1, o);
      s2 += __shfl_down_sync(0xffffffffu, s2, o);
    }
    if (flane == 0 && fw < BB) {
      red[fw]   = 0.5f*(a1/(s1 + 1e-10f) + a2/(s2 + 1e-10f));
      red[8+fw] = p;
    }
    __syncthreads();
    if (tid == 0) {
      float ta=0, tp=0;
#pragma unroll
      for (int i = 0; i < BB; i++) { ta += red[i]; tp += red[8+i]; }
      out[0] = ta / (float)BB;
      out[1] = tp / (float)(BB*NN);
      g_cnt = 0;                       // reset ticket for next graph replay
    }
  }
}

extern "C" void kernel_launch(void* const* d_in, const int* in_sizes, int n_in,
                              void* d_out, int out_size) {
  const float* z1 = (const float*)d_in[0];
  const float* z2 = (const float*)d_in[1];
  const float* w1 = (const float*)d_in[2];
  const float* w2 = (const float*)d_in[3];
  float* out = (float*)d_out;

  static int once = 0;
  if (!once) {
    cudaFuncSetAttribute(align_kernel,
        cudaFuncAttributeMaxDynamicSharedMemorySize, SMEMF*4);
    once = 1;
  }
  dim3 grid(12, 6, BB);   // 576 blocks; tile = 16x8 tokens
  align_kernel<<<grid, 256, SMEMF*4>>>(z1, z2, w1, w2, out);
}

// round 12
// speedup vs baseline: 1.0774x; 1.0774x over previous
#include <cuda_runtime.h>
#include <cstdint>
#include <math.h>

#define BB 8
#define HH 96
#define WW 96
#define DD 768
#define NN (HH*WW)
#define STR 36             // smem row stride (floats), ==4 mod 32 -> conflict-free frags
#define AROWS 128
#define ROWS 368           // 128 A rows + 240 B halo rows (20x12)
#define BUFF (ROWS*STR)    // 13248 floats per buffer
#define NCHK 24            // K chunks of 32 floats
#define S_NRM (2*BUFF)
#define S_RED (S_NRM+ROWS)
#define SMEMF (S_RED+48)   // 26912 floats = 107648 B
#define SIMSTR 76
#define NBLK 576
#define TFM(x) __uint_as_float(__float_as_uint(x) & 0xFFFFE000u)

__device__ float g_part[5][NBLK];
__device__ int g_cnt = 0;
extern __shared__ float smem[];

__device__ __forceinline__ void mma8(float* d, uint32_t a0, uint32_t a1,
                                     uint32_t a2, uint32_t a3,
                                     uint32_t b0, uint32_t b1) {
  asm volatile(
    "mma.sync.aligned.m16n8k8.row.col.f32.tf32.tf32.f32 "
    "{%0,%1,%2,%3}, {%4,%5,%6,%7}, {%8,%9}, {%0,%1,%2,%3};"
    : "+f"(d[0]), "+f"(d[1]), "+f"(d[2]), "+f"(d[3])
    : "r"(a0), "r"(a1), "r"(a2), "r"(a3), "r"(b0), "r"(b1));
}

__global__ void __launch_bounds__(256, 2)
align_kernel(const float* __restrict__ z1, const float* __restrict__ z2,
             const float* __restrict__ w1, const float* __restrict__ w2,
             float* __restrict__ out)
{
  const int tid = threadIdx.x, w = tid >> 5, lane = tid & 31, lane8 = tid & 7;
  const int b = blockIdx.z, th0 = blockIdx.y * 16, tw0 = blockIdx.x * 8;

  // ---- A staging: affine in slot k (rows arow+32k, k=0..3) -----------------
  const int arow = tid >> 3;
  const int aty  = tid >> 6;
  const int atx  = (tid >> 3) & 7;
  const int agBase  = (b*NN + (th0+aty)*WW + tw0+atx)*DD + lane8*4;
  const int agStep  = 4*WW*DD;
  const int sofBase = arow*STR + lane8*4;
  const int sofStep = 32*STR;

  // ---- B staging: slot k=0..7 -> halo row n = arow + 32k -------------------
  int bg[8];
#pragma unroll
  for (int k = 0; k < 8; k++) {
    int n = arow + 32*k;
    if (n < 240) {
      int r = n/12, cl = n - 12*r;
      int gh = th0 + r - 2, gw = tw0 + cl - 2;
      bool inb = ((unsigned)gh < HH) && ((unsigned)gw < WW);
      bg[k] = inb ? (b*NN + gh*WW + gw)*DD + lane8*4 : -1;
    } else bg[k] = -2;
  }
  float nrmA[4] = {0,0,0,0};
  float nrmB[8] = {0,0,0,0,0,0,0,0};
  float acc[9][4];
#pragma unroll
  for (int j = 0; j < 9; j++)
#pragma unroll
    for (int i = 0; i < 4; i++) acc[j][i] = 0.f;

  const int aOff = (16*w + (lane >> 2))*STR + (lane & 3);
  const int bOff = (AROWS + 24*w + (lane >> 2))*STR + (lane & 3);

  // ---- prologue: zero OOB halo rows in BOTH buffers ------------------------
#pragma unroll
  for (int k = 0; k < 8; k++)
    if (bg[k] == -1) {
      int sof = sofBase + (4+k)*sofStep;
      *(float4*)(smem + sof)        = make_float4(0.f,0.f,0.f,0.f);
      *(float4*)(smem + BUFF + sof) = make_float4(0.f,0.f,0.f,0.f);
    }
  // stage chunk 0 into buf0
#pragma unroll
  for (int k = 0; k < 4; k++) {
    float4 v = *(const float4*)(z1 + agBase + k*agStep);
    v.x=TFM(v.x); v.y=TFM(v.y); v.z=TFM(v.z); v.w=TFM(v.w);
    nrmA[k] += v.x*v.x + v.y*v.y + v.z*v.z + v.w*v.w;
    *(float4*)(smem + sofBase + k*sofStep) = v;
  }
#pragma unroll
  for (int k = 0; k < 8; k++)
    if (bg[k] >= 0) {
      float4 v = *(const float4*)(z2 + bg[k]);
      v.x=TFM(v.x); v.y=TFM(v.y); v.z=TFM(v.z); v.w=TFM(v.w);
      nrmB[k] += v.x*v.x + v.y*v.y + v.z*v.z + v.w*v.w;
      *(float4*)(smem + sofBase + (4+k)*sofStep) = v;
    }
  __syncthreads();

  // ---- main loop: 2-phase register prefetch interleaved with MMA halves ----
#pragma unroll 1
  for (int c = 0; c < NCHK; c++) {
    const uint32_t* A = (const uint32_t*)(smem + (c & 1)*BUFF) + aOff;
    const uint32_t* B = (const uint32_t*)(smem + (c & 1)*BUFF) + bOff;
    float* nb = smem + ((c + 1) & 1)*BUFF;
    const bool more = (c + 1 < NCHK);
    const int co = (c + 1)*32;
    float4 zb[6];

    // phase-A prefetch: A slots 0..3 + B slots 0..1
    if (more) {
#pragma unroll
      for (int k = 0; k < 4; k++)
        zb[k] = *(const float4*)(z1 + agBase + k*agStep + co);
#pragma unroll
      for (int k = 0; k < 2; k++)
        if (bg[k] >= 0) zb[4+k] = *(const float4*)(z2 + bg[k] + co);
    }
    // MMA kt = 0,1
#pragma unroll
    for (int kt = 0; kt < 2; kt++) {
      uint32_t a0 = A[kt*8],     a1 = A[8*STR + kt*8];
      uint32_t a2 = A[kt*8 + 4], a3 = A[8*STR + kt*8 + 4];
#pragma unroll
      for (int j = 0; j < 9; j++)
        mma8(acc[j], a0, a1, a2, a3, B[j*8*STR + kt*8], B[j*8*STR + kt*8 + 4]);
    }
    // STS phase-A + prefetch phase-B (B slots 2..7)
    if (more) {
#pragma unroll
      for (int k = 0; k < 4; k++) {
        float4 v = zb[k];
        v.x=TFM(v.x); v.y=TFM(v.y); v.z=TFM(v.z); v.w=TFM(v.w);
        nrmA[k] += v.x*v.x + v.y*v.y + v.z*v.z + v.w*v.w;
        *(float4*)(nb + sofBase + k*sofStep) = v;
      }
#pragma unroll
      for (int k = 0; k < 2; k++)
        if (bg[k] >= 0) {
          float4 v = zb[4+k];
          v.x=TFM(v.x); v.y=TFM(v.y); v.z=TFM(v.z); v.w=TFM(v.w);
          nrmB[k] += v.x*v.x + v.y*v.y + v.z*v.z + v.w*v.w;
          *(float4*)(nb + sofBase + (4+k)*sofStep) = v;
        }
#pragma unroll
      for (int k = 2; k < 8; k++)
        if (bg[k] >= 0) zb[k-2] = *(const float4*)(z2 + bg[k] + co);
    }
    // MMA kt = 2,3
#pragma unroll
    for (int kt = 2; kt < 4; kt++) {
      uint32_t a0 = A[kt*8],     a1 = A[8*STR + kt*8];
      uint32_t a2 = A[kt*8 + 4], a3 = A[8*STR + kt*8 + 4];
#pragma unroll
      for (int j = 0; j < 9; j++)
        mma8(acc[j], a0, a1, a2, a3, B[j*8*STR + kt*8], B[j*8*STR + kt*8 + 4]);
    }
    // STS phase-B
    if (more) {
#pragma unroll
      for (int k = 2; k < 8; k++)
        if (bg[k] >= 0) {
          float4 v = zb[k-2];
          v.x=TFM(v.x); v.y=TFM(v.y); v.z=TFM(v.z); v.w=TFM(v.w);
          nrmB[k] += v.x*v.x + v.y*v.y + v.z*v.z + v.w*v.w;
          *(float4*)(nb + sofBase + (4+k)*sofStep) = v;
        }
    }
    __syncthreads();
  }

  // ---- norms: reduce 8 lanes per row -> S_NRM ------------------------------
#pragma unroll
  for (int k = 0; k < 4; k++) {
    float r = nrmA[k];
    r += __shfl_down_sync(0xffffffffu, r, 4);
    r += __shfl_down_sync(0xffffffffu, r, 2);
    r += __shfl_down_sync(0xffffffffu, r, 1);
    if (lane8 == 0) smem[S_NRM + arow + 32*k] = r;
  }
#pragma unroll
  for (int k = 0; k < 8; k++) {
    float r = nrmB[k];
    r += __shfl_down_sync(0xffffffffu, r, 4);
    r += __shfl_down_sync(0xffffffffu, r, 2);
    r += __shfl_down_sync(0xffffffffu, r, 1);
    int row = AROWS + arow + 32*k;
    if (lane8 == 0 && row < ROWS) smem[S_NRM + row] = r;
  }

  // ---- sims -> smem (reuse buf0 region), stride 76 -------------------------
  {
    float* sims = smem;
    int row0 = 16*w + (lane >> 2);
    int cc = 2*(lane & 3);
#pragma unroll
    for (int j = 0; j < 9; j++) {
      *(float2*)(sims + row0*SIMSTR + 8*j + cc)     = make_float2(acc[j][0], acc[j][1]);
      *(float2*)(sims + (row0+8)*SIMSTR + 8*j + cc) = make_float2(acc[j][2], acc[j][3]);
    }
  }
  __syncthreads();

  for (int t = tid; t < ROWS; t += 256) {
    float v = smem[S_NRM + t];
    smem[S_NRM + t] = 1.f / fmaxf(sqrtf(v), 1e-12f);
  }
  __syncthreads();

  // ---- epilogue: per-token 25-shift softmax + weighted partials ------------
  float pA1 = 0.f, pA2 = 0.f, pP = 0.f, pS1 = 0.f, pS2 = 0.f;
  if (tid < AROWS) {
    int m = tid, ty = m >> 3, tx = m & 7;
    int mw = m >> 4;
    int tprime = (m >> 3) & 1;
    const float inv1 = smem[S_NRM + m];
    const float* srow = smem + m*SIMSTR;
    const float* invB = smem + S_NRM + AROWS + 24*mw;
    float sn[25], mx = -1e30f;
#pragma unroll
    for (int dy = 0; dy < 5; dy++)
#pragma unroll
      for (int dx = 0; dx < 5; dx++) {
        int nl = (tprime + dy)*12 + tx + dx;
        float v = srow[nl] * inv1 * invB[nl];
        sn[dy*5 + dx] = v; mx = fmaxf(mx, v);
      }
    float se = 0.f, sv = 0.f;
    const float invT = 1.f / 0.07f;
#pragma unroll
    for (int s = 0; s < 25; s++) {
      float e = __expf((sn[s] - mx) * invT);
      se += e; sv += e * sn[s];
    }
    float sb = sv / se;
    int tok = (th0 + ty)*WW + tw0 + tx;
    float wv1 = w1[b*NN + tok], wv2 = w2[b*NN + tok];
    pA1 = (1.f - sb)*wv1; pA2 = (1.f - sb)*wv2; pP = sb; pS1 = wv1; pS2 = wv2;
  }
#pragma unroll
  for (int o = 16; o > 0; o >>= 1) {
    pA1 += __shfl_down_sync(0xffffffffu, pA1, o);
    pA2 += __shfl_down_sync(0xffffffffu, pA2, o);
    pP  += __shfl_down_sync(0xffffffffu, pP,  o);
    pS1 += __shfl_down_sync(0xffffffffu, pS1, o);
    pS2 += __shfl_down_sync(0xffffffffu, pS2, o);
  }
  float* red = smem + S_RED;
  if (lane == 0) {
    red[w] = pA1; red[8+w] = pA2; red[16+w] = pP; red[24+w] = pS1; red[32+w] = pS2;
  }
  __syncthreads();
  if (tid == 0) {
    float a1=0,a2=0,p=0,s1=0,s2=0;
#pragma unroll
    for (int i = 0; i < 8; i++) {
      a1+=red[i]; a2+=red[8+i]; p+=red[16+i]; s1+=red[24+i]; s2+=red[32+i];
    }
    int bid = blockIdx.x + 12*blockIdx.y + 72*blockIdx.z;
    g_part[0][bid]=a1; g_part[1][bid]=a2; g_part[2][bid]=p;
    g_part[3][bid]=s1; g_part[4][bid]=s2;
    __threadfence();
    int t = atomicAdd(&g_cnt, 1);
    red[45] = (t == NBLK-1) ? 1.f : 0.f;
  }
  __syncthreads();

  // ---- last block performs the deterministic final reduction ---------------
  if (red[45] != 0.f) {
    int fw = tid >> 5, flane = tid & 31;
    float a1=0,a2=0,p=0,s1=0,s2=0;
    if (fw < BB) {
      for (int i = flane; i < 72; i += 32) {
        int bid = fw*72 + i;
        a1 += g_part[0][bid]; a2 += g_part[1][bid]; p += g_part[2][bid];
        s1 += g_part[3][bid]; s2 += g_part[4][bid];
      }
    }
#pragma unroll
    for (int o = 16; o > 0; o >>= 1) {
      a1 += __shfl_down_sync(0xffffffffu, a1, o);
      a2 += __shfl_down_sync(0xffffffffu, a2, o);
      p  += __shfl_down_sync(0xffffffffu, p,  o);
      s1 += __shfl_down_sync(0xffffffffu, s1, o);
      s2 += __shfl_down_sync(0xffffffffu, s2, o);
    }
    if (flane == 0 && fw < BB) {
      red[fw]   = 0.5f*(a1/(s1 + 1e-10f) + a2/(s2 + 1e-10f));
      red[8+fw] = p;
    }
    __syncthreads();
    if (tid == 0) {
      float ta=0, tp=0;
#pragma unroll
      for (int i = 0; i < BB; i++) { ta += red[i]; tp += red[8+i]; }
      out[0] = ta / (float)BB;
      out[1] = tp / (float)(BB*NN);
      g_cnt = 0;                       // reset ticket for next graph replay
    }
  }
}

extern "C" void kernel_launch(void* const* d_in, const int* in_sizes, int n_in,
                              void* d_out, int out_size) {
  const float* z1 = (const float*)d_in[0];
  const float* z2 = (const float*)d_in[1];
  const float* w1 = (const float*)d_in[2];
  const float* w2 = (const float*)d_in[3];
  float* out = (float*)d_out;

  static int once = 0;
  if (!once) {
    cudaFuncSetAttribute(align_kernel,
        cudaFuncAttributeMaxDynamicSharedMemorySize, SMEMF*4);
    once = 1;
  }
  dim3 grid(12, 6, BB);   // 576 blocks; tile = 16x8 tokens
  align_kernel<<<grid, 256, SMEMF*4>>>(z1, z2, w1, w2, out);
}

// round 13
// speedup vs baseline: 1.3908x; 1.2909x over previous
#include <cuda_runtime.h>
#include <cuda_bf16.h>
#include <cstdint>
#include <math.h>

#define BB 8
#define HH 96
#define WW 96
#define DD 768
#define NN (HH*WW)
#define STRU 20            // uint32 row stride: 16 data words + 4 pad (conflict-free)
#define AROWS 128
#define ROWS 368           // 128 A rows + 240 B halo rows (20x12)
#define BUFFU (ROWS*STRU)  // 7360 words per buffer
#define NCHK 24            // K chunks of 32 floats (= 16 bf16x2 words)
#define S_NRM (2*BUFFU)    // word offset of norm scratch
#define S_RED (S_NRM+ROWS)
#define SMEMW (S_RED+48)   // 15136 words = 60544 B
#define SIMSTR 76
#define NBLK 576

__device__ float g_part[5][NBLK];
__device__ int g_cnt = 0;
extern __shared__ uint32_t smemw[];

__device__ __forceinline__ void mma16(float* d, uint32_t a0, uint32_t a1,
                                      uint32_t a2, uint32_t a3,
                                      uint32_t b0, uint32_t b1) {
  asm volatile(
    "mma.sync.aligned.m16n8k16.row.col.f32.bf16.bf16.f32 "
    "{%0,%1,%2,%3}, {%4,%5,%6,%7}, {%8,%9}, {%0,%1,%2,%3};"
    : "+f"(d[0]), "+f"(d[1]), "+f"(d[2]), "+f"(d[3])
    : "r"(a0), "r"(a1), "r"(a2), "r"(a3), "r"(b0), "r"(b1));
}

__device__ __forceinline__ uint2 cvt2(float4 v) {
  __nv_bfloat162 lo = __float22bfloat162_rn(make_float2(v.x, v.y));
  __nv_bfloat162 hi = __float22bfloat162_rn(make_float2(v.z, v.w));
  uint2 r;
  r.x = *(uint32_t*)&lo;
  r.y = *(uint32_t*)&hi;
  return r;
}

__global__ void __launch_bounds__(256, 2)
align_kernel(const float* __restrict__ z1, const float* __restrict__ z2,
             const float* __restrict__ w1, const float* __restrict__ w2,
             float* __restrict__ out)
{
  float* smemf = (float*)smemw;
  const int tid = threadIdx.x, w = tid >> 5, lane = tid & 31, lane8 = tid & 7;
  const int b = blockIdx.z, th0 = blockIdx.y * 16, tw0 = blockIdx.x * 8;

  // ---- A staging: affine in slot k (rows arow+32k, k=0..3) -----------------
  const int arow = tid >> 3;
  const int aty  = tid >> 6;
  const int atx  = (tid >> 3) & 7;
  const int agBase  = (b*NN + (th0+aty)*WW + tw0+atx)*DD + lane8*4;
  const int agStep  = 4*WW*DD;
  const int sofBase = arow*STRU + lane8*2;   // word units (bf16x2)
  const int sofStep = 32*STRU;

  // ---- B staging: slot k=0..7 -> halo row n = arow + 32k -------------------
  int bg[8];
#pragma unroll
  for (int k = 0; k < 8; k++) {
    int n = arow + 32*k;
    if (n < 240) {
      int r = n/12, cl = n - 12*r;
      int gh = th0 + r - 2, gw = tw0 + cl - 2;
      bool inb = ((unsigned)gh < HH) && ((unsigned)gw < WW);
      bg[k] = inb ? (b*NN + gh*WW + gw)*DD + lane8*4 : -1;
    } else bg[k] = -2;
  }
  float nrmA[4] = {0,0,0,0};
  float nrmB[8] = {0,0,0,0,0,0,0,0};
  float acc[9][4];
#pragma unroll
  for (int j = 0; j < 9; j++)
#pragma unroll
    for (int i = 0; i < 4; i++) acc[j][i] = 0.f;

  const int aOff = (16*w + (lane >> 2))*STRU + (lane & 3);
  const int bOff = (AROWS + 24*w + (lane >> 2))*STRU + (lane & 3);

  // ---- prologue: zero OOB halo rows in BOTH buffers ------------------------
#pragma unroll
  for (int k = 0; k < 8; k++)
    if (bg[k] == -1) {
      int sof = sofBase + (4+k)*sofStep;
      *(uint2*)(smemw + sof)         = make_uint2(0u, 0u);
      *(uint2*)(smemw + BUFFU + sof) = make_uint2(0u, 0u);
    }
  // stage chunk 0 into buf0
#pragma unroll
  for (int k = 0; k < 4; k++) {
    float4 v = *(const float4*)(z1 + agBase + k*agStep);
    nrmA[k] += v.x*v.x + v.y*v.y + v.z*v.z + v.w*v.w;
    *(uint2*)(smemw + sofBase + k*sofStep) = cvt2(v);
  }
#pragma unroll
  for (int k = 0; k < 8; k++)
    if (bg[k] >= 0) {
      float4 v = *(const float4*)(z2 + bg[k]);
      nrmB[k] += v.x*v.x + v.y*v.y + v.z*v.z + v.w*v.w;
      *(uint2*)(smemw + sofBase + (4+k)*sofStep) = cvt2(v);
    }
  __syncthreads();

  // ---- main loop: 2-phase register prefetch interleaved with MMA halves ----
#pragma unroll 1
  for (int c = 0; c < NCHK; c++) {
    const uint32_t* A = smemw + (c & 1)*BUFFU + aOff;
    const uint32_t* B = smemw + (c & 1)*BUFFU + bOff;
    uint32_t* nb = smemw + ((c + 1) & 1)*BUFFU;
    const bool more = (c + 1 < NCHK);
    const int co = (c + 1)*32;
    float4 zb[6];

    // phase-A prefetch: A slots 0..3 + B slots 0..1
    if (more) {
#pragma unroll
      for (int k = 0; k < 4; k++)
        zb[k] = *(const float4*)(z1 + agBase + k*agStep + co);
#pragma unroll
      for (int k = 0; k < 2; k++)
        if (bg[k] >= 0) zb[4+k] = *(const float4*)(z2 + bg[k] + co);
    }
    // MMA k16-tile t = 0
    {
      uint32_t a0 = A[0], a1 = A[8*STRU], a2 = A[4], a3 = A[8*STRU + 4];
#pragma unroll
      for (int j = 0; j < 9; j++)
        mma16(acc[j], a0, a1, a2, a3, B[j*8*STRU], B[j*8*STRU + 4]);
    }
    // STS phase-A + prefetch phase-B (B slots 2..7)
    if (more) {
#pragma unroll
      for (int k = 0; k < 4; k++) {
        float4 v = zb[k];
        nrmA[k] += v.x*v.x + v.y*v.y + v.z*v.z + v.w*v.w;
        *(uint2*)(nb + sofBase + k*sofStep) = cvt2(v);
      }
#pragma unroll
      for (int k = 0; k < 2; k++)
        if (bg[k] >= 0) {
          float4 v = zb[4+k];
          nrmB[k] += v.x*v.x + v.y*v.y + v.z*v.z + v.w*v.w;
          *(uint2*)(nb + sofBase + (4+k)*sofStep) = cvt2(v);
        }
#pragma unroll
      for (int k = 2; k < 8; k++)
        if (bg[k] >= 0) zb[k-2] = *(const float4*)(z2 + bg[k] + co);
    }
    // MMA k16-tile t = 1
    {
      uint32_t a0 = A[8], a1 = A[8*STRU + 8], a2 = A[12], a3 = A[8*STRU + 12];
#pragma unroll
      for (int j = 0; j < 9; j++)
        mma16(acc[j], a0, a1, a2, a3, B[j*8*STRU + 8], B[j*8*STRU + 12]);
    }
    // STS phase-B
    if (more) {
#pragma unroll
      for (int k = 2; k < 8; k++)
        if (bg[k] >= 0) {
          float4 v = zb[k-2];
          nrmB[k] += v.x*v.x + v.y*v.y + v.z*v.z + v.w*v.w;
          *(uint2*)(nb + sofBase + (4+k)*sofStep) = cvt2(v);
        }
    }
    __syncthreads();
  }

  // ---- norms: reduce 8 lanes per row -> S_NRM ------------------------------
#pragma unroll
  for (int k = 0; k < 4; k++) {
    float r = nrmA[k];
    r += __shfl_down_sync(0xffffffffu, r, 4);
    r += __shfl_down_sync(0xffffffffu, r, 2);
    r += __shfl_down_sync(0xffffffffu, r, 1);
    if (lane8 == 0) smemf[S_NRM + arow + 32*k] = r;
  }
#pragma unroll
  for (int k = 0; k < 8; k++) {
    float r = nrmB[k];
    r += __shfl_down_sync(0xffffffffu, r, 4);
    r += __shfl_down_sync(0xffffffffu, r, 2);
    r += __shfl_down_sync(0xffffffffu, r, 1);
    int row = AROWS + arow + 32*k;
    if (lane8 == 0 && row < ROWS) smemf[S_NRM + row] = r;
  }

  // ---- sims -> smem (reuse buffer region), stride 76 -----------------------
  {
    int row0 = 16*w + (lane >> 2);
    int cc = 2*(lane & 3);
#pragma unroll
    for (int j = 0; j < 9; j++) {
      *(float2*)(smemf + row0*SIMSTR + 8*j + cc)     = make_float2(acc[j][0], acc[j][1]);
      *(float2*)(smemf + (row0+8)*SIMSTR + 8*j + cc) = make_float2(acc[j][2], acc[j][3]);
    }
  }
  __syncthreads();

  for (int t = tid; t < ROWS; t += 256) {
    float v = smemf[S_NRM + t];
    smemf[S_NRM + t] = 1.f / fmaxf(sqrtf(v), 1e-12f);
  }
  __syncthreads();

  // ---- epilogue: per-token 25-shift softmax + weighted partials ------------
  float pA1 = 0.f, pA2 = 0.f, pP = 0.f, pS1 = 0.f, pS2 = 0.f;
  if (tid < AROWS) {
    int m = tid, ty = m >> 3, tx = m & 7;
    int mw = m >> 4;
    int tprime = (m >> 3) & 1;
    const float inv1 = smemf[S_NRM + m];
    const float* srow = smemf + m*SIMSTR;
    const float* invB = smemf + S_NRM + AROWS + 24*mw;
    float sn[25], mx = -1e30f;
#pragma unroll
    for (int dy = 0; dy < 5; dy++)
#pragma unroll
      for (int dx = 0; dx < 5; dx++) {
        int nl = (tprime + dy)*12 + tx + dx;
        float v = srow[nl] * inv1 * invB[nl];
        sn[dy*5 + dx] = v; mx = fmaxf(mx, v);
      }
    float se = 0.f, sv = 0.f;
    const float invT = 1.f / 0.07f;
#pragma unroll
    for (int s = 0; s < 25; s++) {
      float e = __expf((sn[s] - mx) * invT);
      se += e; sv += e * sn[s];
    }
    float sb = sv / se;
    int tok = (th0 + ty)*WW + tw0 + tx;
    float wv1 = w1[b*NN + tok], wv2 = w2[b*NN + tok];
    pA1 = (1.f - sb)*wv1; pA2 = (1.f - sb)*wv2; pP = sb; pS1 = wv1; pS2 = wv2;
  }
#pragma unroll
  for (int o = 16; o > 0; o >>= 1) {
    pA1 += __shfl_down_sync(0xffffffffu, pA1, o);
    pA2 += __shfl_down_sync(0xffffffffu, pA2, o);
    pP  += __shfl_down_sync(0xffffffffu, pP,  o);
    pS1 += __shfl_down_sync(0xffffffffu, pS1, o);
    pS2 += __shfl_down_sync(0xffffffffu, pS2, o);
  }
  float* red = smemf + S_RED;
  if (lane == 0) {
    red[w] = pA1; red[8+w] = pA2; red[16+w] = pP; red[24+w] = pS1; red[32+w] = pS2;
  }
  __syncthreads();
  if (tid == 0) {
    float a1=0,a2=0,p=0,s1=0,s2=0;
#pragma unroll
    for (int i = 0; i < 8; i++) {
      a1+=red[i]; a2+=red[8+i]; p+=red[16+i]; s1+=red[24+i]; s2+=red[32+i];
    }
    int bid = blockIdx.x + 12*blockIdx.y + 72*blockIdx.z;
    g_part[0][bid]=a1; g_part[1][bid]=a2; g_part[2][bid]=p;
    g_part[3][bid]=s1; g_part[4][bid]=s2;
    __threadfence();
    int t = atomicAdd(&g_cnt, 1);
    red[45] = (t == NBLK-1) ? 1.f : 0.f;
  }
  __syncthreads();

  // ---- last block performs the deterministic final reduction ---------------
  if (red[45] != 0.f) {
    int fw = tid >> 5, flane = tid & 31;
    float a1=0,a2=0,p=0,s1=0,s2=0;
    if (fw < BB) {
      for (int i = flane; i < 72; i += 32) {
        int bid = fw*72 + i;
        a1 += g_part[0][bid]; a2 += g_part[1][bid]; p += g_part[2][bid];
        s1 += g_part[3][bid]; s2 += g_part[4][bid];
      }
    }
#pragma unroll
    for (int o = 16; o > 0; o >>= 1) {
      a1 += __shfl_down_sync(0xffffffffu, a1, o);
      a2 += __shfl_down_sync(0xffffffffu, a2, o);
      p  += __shfl_down_sync(0xffffffffu, p,  o);
      s1 += __shfl_down_sync(0xffffffffu, s1, o);
      s2 += __shfl_down_sync(0xffffffffu, s2, o);
    }
    if (flane == 0 && fw < BB) {
      red[fw]   = 0.5f*(a1/(s1 + 1e-10f) + a2/(s2 + 1e-10f));
      red[8+fw] = p;
    }
    __syncthreads();
    if (tid == 0) {
      float ta=0, tp=0;
#pragma unroll
      for (int i = 0; i < BB; i++) { ta += red[i]; tp += red[8+i]; }
      out[0] = ta / (float)BB;
      out[1] = tp / (float)(BB*NN);
      g_cnt = 0;                       // reset ticket for next graph replay
    }
  }
}

extern "C" void kernel_launch(void* const* d_in, const int* in_sizes, int n_in,
                              void* d_out, int out_size) {
  const float* z1 = (const float*)d_in[0];
  const float* z2 = (const float*)d_in[1];
  const float* w1 = (const float*)d_in[2];
  const float* w2 = (const float*)d_in[3];
  float* out = (float*)d_out;

  static int once = 0;
  if (!once) {
    cudaFuncSetAttribute(align_kernel,
        cudaFuncAttributeMaxDynamicSharedMemorySize, SMEMW*4);
    once = 1;
  }
  dim3 grid(12, 6, BB);   // 576 blocks; tile = 16x8 tokens
  align_kernel<<<grid, 256, SMEMW*4>>>(z1, z2, w1, w2, out);
}

// round 16
// speedup vs baseline: 1.5760x; 1.1332x over previous
#include <cuda_runtime.h>
#include <cstdint>
#include <math.h>

#define BB 8
#define HH 96
#define WW 96
#define DD 768
#define NN (HH*WW)
#define STR 36             // fp32 smem row stride (36 ==4 mod 32 -> conflict-free frags)
#define AROWS 128
#define ROWS 368           // 128 A rows + 240 B halo rows (20x12)
#define BUFF (ROWS*STR)    // 13248 floats per buffer
#define NCHK 24            // K chunks of 32 floats
#define S_NRM (2*BUFF)
#define S_RED (S_NRM+ROWS)
#define SMEMF (S_RED+48)   // 26912 floats = 107648 B  (2 blocks/SM fit)
#define SIMSTR 76
#define NBLK 576

__device__ float g_part[5][NBLK];
__device__ int g_cnt = 0;
extern __shared__ float smemf[];

__device__ __forceinline__ uint32_t s2u(const void* p){ uint32_t a;
  asm("{ .reg .u64 t; cvta.to.shared.u64 t, %1; cvt.u32.u64 %0, t; }":"=r"(a):"l"(p)); return a; }
__device__ __forceinline__ void cpa(uint32_t dst, const float* src) {
  asm volatile("cp.async.cg.shared.global [%0], [%1], 16;" :: "r"(dst), "l"(src) : "memory");
}
#define CPCOMMIT() asm volatile("cp.async.commit_group;" ::: "memory")
#define CPWAIT0()  asm volatile("cp.async.wait_group 0;" ::: "memory")

__device__ __forceinline__ void mma8(float* d, uint32_t a0, uint32_t a1,
                                     uint32_t a2, uint32_t a3,
                                     uint32_t b0, uint32_t b1) {
  asm volatile(
    "mma.sync.aligned.m16n8k8.row.col.f32.tf32.tf32.f32 "
    "{%0,%1,%2,%3}, {%4,%5,%6,%7}, {%8,%9}, {%0,%1,%2,%3};"
    : "+f"(d[0]), "+f"(d[1]), "+f"(d[2]), "+f"(d[3])
    : "r"(a0), "r"(a1), "r"(a2), "r"(a3), "r"(b0), "r"(b1));
}

__global__ void __launch_bounds__(256, 2)
align_kernel(const float* __restrict__ z1, const float* __restrict__ z2,
             const float* __restrict__ w1, const float* __restrict__ w2,
             float* __restrict__ out)
{
  const int tid = threadIdx.x, w = tid >> 5, lane = tid & 31, lane8 = tid & 7;
  const int b = blockIdx.z, th0 = blockIdx.y * 16, tw0 = blockIdx.x * 8;
  const uint32_t sbase = s2u(smemf);

  // ---- staging maps: slot k covers row arow+32k, 8 lanes x 16B per row -----
  const int arow = tid >> 3;
  const int aty  = tid >> 6;              // arow>>3
  const int atx  = (tid >> 3) & 7;
  const int agBase  = (b*NN + (th0+aty)*WW + tw0+atx)*DD + lane8*4;
  const int agStep  = 4*WW*DD;            // +4 token rows per slot
  const int sofBase = arow*STR + lane8*4; // float units
  const int sofStep = 32*STR;

  int bg[8];
#pragma unroll
  for (int k = 0; k < 8; k++) {
    int n = arow + 32*k;
    if (n < 240) {
      int r = n/12, cl = n - 12*r;
      int gh = th0 + r - 2, gw = tw0 + cl - 2;
      bool inb = ((unsigned)gh < HH) && ((unsigned)gw < WW);
      bg[k] = inb ? (b*NN + gh*WW + gw)*DD + lane8*4 : -1;
    } else bg[k] = -2;
  }
  float nA0 = 0.f, nA1 = 0.f, nBp[9];
#pragma unroll
  for (int j = 0; j < 9; j++) nBp[j] = 0.f;
  float acc[9][4];
#pragma unroll
  for (int j = 0; j < 9; j++)
#pragma unroll
    for (int i = 0; i < 4; i++) acc[j][i] = 0.f;

  const int aOff = (16*w + (lane >> 2))*STR + (lane & 3);
  const int bOff = (AROWS + 24*w + (lane >> 2))*STR + (lane & 3);

  // ---- prologue: zero OOB halo rows in BOTH buffers; cp.async chunk 0 ------
#pragma unroll
  for (int k = 0; k < 8; k++)
    if (bg[k] == -1) {
      int sof = sofBase + (4+k)*sofStep;
      *(float4*)(smemf + sof)        = make_float4(0.f,0.f,0.f,0.f);
      *(float4*)(smemf + BUFF + sof) = make_float4(0.f,0.f,0.f,0.f);
    }
#pragma unroll
  for (int k = 0; k < 4; k++)
    cpa(sbase + (sofBase + k*sofStep)*4, z1 + agBase + k*agStep);
#pragma unroll
  for (int k = 0; k < 8; k++)
    if (bg[k] >= 0)
      cpa(sbase + (sofBase + (4+k)*sofStep)*4, z2 + bg[k]);
  CPCOMMIT();
  CPWAIT0();
  __syncthreads();

  // ---- main loop -----------------------------------------------------------
#pragma unroll 1
  for (int c = 0; c < NCHK; c++) {
    const bool more = (c + 1 < NCHK);
    // issue cp.async for chunk c+1 into the other buffer
    if (more) {
      const int co = (c + 1)*32;
      const uint32_t nb = sbase + (((c+1) & 1)*BUFF)*4;
#pragma unroll
      for (int k = 0; k < 4; k++)
        cpa(nb + (sofBase + k*sofStep)*4, z1 + agBase + k*agStep + co);
#pragma unroll
      for (int k = 0; k < 8; k++)
        if (bg[k] >= 0)
          cpa(nb + (sofBase + (4+k)*sofStep)*4, z2 + bg[k] + co);
    }
    CPCOMMIT();

    const uint32_t* A = (const uint32_t*)(smemf + (c & 1)*BUFF) + aOff;
    const uint32_t* B = (const uint32_t*)(smemf + (c & 1)*BUFF) + bOff;
#pragma unroll
    for (int kt = 0; kt < 4; kt++) {
      uint32_t a0 = A[kt*8],     a1 = A[8*STR + kt*8];
      uint32_t a2 = A[kt*8 + 4], a3 = A[8*STR + kt*8 + 4];
      float f0 = __uint_as_float(a0), f1 = __uint_as_float(a1);
      float f2 = __uint_as_float(a2), f3 = __uint_as_float(a3);
      nA0 += f0*f0 + f2*f2;
      nA1 += f1*f1 + f3*f3;
#pragma unroll
      for (int j = 0; j < 9; j++) {
        uint32_t b0 = B[j*8*STR + kt*8];
        uint32_t b1 = B[j*8*STR + kt*8 + 4];
        float g0 = __uint_as_float(b0), g1 = __uint_as_float(b1);
        nBp[j] += g0*g0 + g1*g1;
        mma8(acc[j], a0, a1, a2, a3, b0, b1);
      }
    }
    CPWAIT0();
    __syncthreads();
  }

  // ---- norms from fragments: reduce over the 4 lanes of each group ---------
  nA0 += __shfl_xor_sync(0xffffffffu, nA0, 1);
  nA0 += __shfl_xor_sync(0xffffffffu, nA0, 2);
  nA1 += __shfl_xor_sync(0xffffffffu, nA1, 1);
  nA1 += __shfl_xor_sync(0xffffffffu, nA1, 2);
  if ((lane & 3) == 0) {
    int g = lane >> 2;
    smemf[S_NRM + 16*w + g]     = nA0;
    smemf[S_NRM + 16*w + 8 + g] = nA1;
  }
#pragma unroll
  for (int j = 0; j < 9; j++) {
    float r = nBp[j];
    r += __shfl_xor_sync(0xffffffffu, r, 1);
    r += __shfl_xor_sync(0xffffffffu, r, 2);
    if ((lane & 3) == 0) {
      int g = lane >> 2;
      int bc = j*8 + g;            // band col 0..71
      int br = bc / 12, cl = bc - 12*br;
      bool doit = (w == 0) ? true : (br >= 4);   // writer dedup rule
      if (doit)
        smemf[S_NRM + AROWS + (2*w + br)*12 + cl] = r;
    }
  }

  // ---- sims -> smem (reuse buffer region), stride 76 -----------------------
  {
    int row0 = 16*w + (lane >> 2);
    int cc = 2*(lane & 3);
#pragma unroll
    for (int j = 0; j < 9; j++) {
      *(float2*)(smemf + row0*SIMSTR + 8*j + cc)     = make_float2(acc[j][0], acc[j][1]);
      *(float2*)(smemf + (row0+8)*SIMSTR + 8*j + cc) = make_float2(acc[j][2], acc[j][3]);
    }
  }
  __syncthreads();

  for (int t = tid; t < ROWS; t += 256) {
    float v = smemf[S_NRM + t];
    smemf[S_NRM + t] = 1.f / fmaxf(sqrtf(v), 1e-12f);
  }
  __syncthreads();

  // ---- epilogue: per-token 25-shift softmax + weighted partials ------------
  float pA1 = 0.f, pA2 = 0.f, pP = 0.f, pS1 = 0.f, pS2 = 0.f;
  if (tid < AROWS) {
    int m = tid, ty = m >> 3, tx = m & 7;
    int mw = m >> 4;
    int tprime = (m >> 3) & 1;
    const float inv1 = smemf[S_NRM + m];
    const float* srow = smemf + m*SIMSTR;
    const float* invB = smemf + S_NRM + AROWS + 24*mw;
    float sn[25], mx = -1e30f;
#pragma unroll
    for (int dy = 0; dy < 5; dy++)
#pragma unroll
      for (int dx = 0; dx < 5; dx++) {
        int nl = (tprime + dy)*12 + tx + dx;
        float v = srow[nl] * inv1 * invB[nl];
        sn[dy*5 + dx] = v; mx = fmaxf(mx, v);
      }
    float se = 0.f, sv = 0.f;
    const float invT = 1.f / 0.07f;
#pragma unroll
    for (int s = 0; s < 25; s++) {
      float e = __expf((sn[s] - mx) * invT);
      se += e; sv += e * sn[s];
    }
    float sb = sv / se;
    int tok = (th0 + ty)*WW + tw0 + tx;
    float wv1 = w1[b*NN + tok], wv2 = w2[b*NN + tok];
    pA1 = (1.f - sb)*wv1; pA2 = (1.f - sb)*wv2; pP = sb; pS1 = wv1; pS2 = wv2;
  }
#pragma unroll
  for (int o = 16; o > 0; o >>= 1) {
    pA1 += __shfl_down_sync(0xffffffffu, pA1, o);
    pA2 += __shfl_down_sync(0xffffffffu, pA2, o);
    pP  += __shfl_down_sync(0xffffffffu, pP,  o);
    pS1 += __shfl_down_sync(0xffffffffu, pS1, o);
    pS2 += __shfl_down_sync(0xffffffffu, pS2, o);
  }
  float* red = smemf + S_RED;
  if (lane == 0) {
    red[w] = pA1; red[8+w] = pA2; red[16+w] = pP; red[24+w] = pS1; red[32+w] = pS2;
  }
  __syncthreads();
  if (tid == 0) {
    float a1=0,a2=0,p=0,s1=0,s2=0;
#pragma unroll
    for (int i = 0; i < 8; i++) {
      a1+=red[i]; a2+=red[8+i]; p+=red[16+i]; s1+=red[24+i]; s2+=red[32+i];
    }
    int bid = blockIdx.x + 12*blockIdx.y + 72*blockIdx.z;
    g_part[0][bid]=a1; g_part[1][bid]=a2; g_part[2][bid]=p;
    g_part[3][bid]=s1; g_part[4][bid]=s2;
    __threadfence();
    int t = atomicAdd(&g_cnt, 1);
    red[45] = (t == NBLK-1) ? 1.f : 0.f;
  }
  __syncthreads();

  // ---- last block performs the deterministic final reduction ---------------
  if (red[45] != 0.f) {
    int fw = tid >> 5, flane = tid & 31;
    float a1=0,a2=0,p=0,s1=0,s2=0;
    if (fw < BB) {
      for (int i = flane; i < 72; i += 32) {
        int bid = fw*72 + i;
        a1 += g_part[0][bid]; a2 += g_part[1][bid]; p += g_part[2][bid];
        s1 += g_part[3][bid]; s2 += g_part[4][bid];
      }
    }
#pragma unroll
    for (int o = 16; o > 0; o >>= 1) {
      a1 += __shfl_down_sync(0xffffffffu, a1, o);
      a2 += __shfl_down_sync(0xffffffffu, a2, o);
      p  += __shfl_down_sync(0xffffffffu, p,  o);
      s1 += __shfl_down_sync(0xffffffffu, s1, o);
      s2 += __shfl_down_sync(0xffffffffu, s2, o);
    }
    if (flane == 0 && fw < BB) {
      red[fw]   = 0.5f*(a1/(s1 + 1e-10f) + a2/(s2 + 1e-10f));
      red[8+fw] = p;
    }
    __syncthreads();
    if (tid == 0) {
      float ta=0, tp=0;
#pragma unroll
      for (int i = 0; i < BB; i++) { ta += red[i]; tp += red[8+i]; }
      out[0] = ta / (float)BB;
      out[1] = tp / (float)(BB*NN);
      g_cnt = 0;                       // reset ticket for next graph replay
    }
  }
}

extern "C" void kernel_launch(void* const* d_in, const int* in_sizes, int n_in,
                              void* d_out, int out_size) {
  const float* z1 = (const float*)d_in[0];
  const float* z2 = (const float*)d_in[1];
  const float* w1 = (const float*)d_in[2];
  const float* w2 = (const float*)d_in[3];
  float* out = (float*)d_out;

  static int once = 0;
  if (!once) {
    cudaFuncSetAttribute(align_kernel,
        cudaFuncAttributeMaxDynamicSharedMemorySize, SMEMF*4);
    once = 1;
  }
  dim3 grid(12, 6, BB);   // 576 blocks; tile = 16x8 tokens
  align_kernel<<<grid, 256, SMEMF*4>>>(z1, z2, w1, w2, out);
}